// round 7
// baseline (speedup 1.0000x reference)
#include <cuda_runtime.h>
#include <cuda_bf16.h>
#include <cstdint>

#define MM 9
#define DD 128
#define NT 32                 // examples per CTA
#define THREADS 256

// ---------------- global scratch (static, no dynamic alloc) ----------------
static __device__ __align__(128) __nv_bfloat16 Whi_g[MM * 128 * 128];
static __device__ __align__(128) __nv_bfloat16 Wlo_g[MM * 128 * 128];

// ---------------- smem layout (bytes) ---------------------------------------
#define SM_WHI 0            // 32768
#define SM_WLO 32768        // 32768
#define SM_FHI 65536        // 8192
#define SM_FLO 73728        // 8192   (FHI..FLO+8K reused as fsum fp32 16KB)
#define SM_G   81920        // 32*9*128 fp32 = 147456
#define SMEM_BYTES 229376

// ---------------- helpers ---------------------------------------------------
// swizzled byte offset of (row, float4-slot q) in a [rows x 128] bf16 tile
__device__ __forceinline__ uint32_t bswz(int row, int q) {
    int c = q >> 1;
    int cs = (c & 8) | ((c & 7) ^ (row & 7));
    return (uint32_t)(row * 256 + cs * 16 + (q & 1) * 8);
}
__device__ __forceinline__ uint32_t lmaddr(uint32_t base, int row, int chunk) {
    int cs = (chunk & 8) | ((chunk & 7) ^ (row & 7));
    return base + (uint32_t)(row * 256 + cs * 16);
}
__device__ __forceinline__ uint32_t smem_u32(const void* p) {
    uint32_t a;
    asm("{ .reg .u64 t; cvta.to.shared.u64 t, %1; cvt.u32.u64 %0, t; }" : "=r"(a) : "l"(p));
    return a;
}
#define LDSM_X4(r0, r1, r2, r3, a) \
    asm volatile("ldmatrix.sync.aligned.m8n8.x4.shared.b16 {%0,%1,%2,%3}, [%4];" \
                 : "=r"(r0), "=r"(r1), "=r"(r2), "=r"(r3) : "r"(a))
#define HMMA(d0, d1, d2, d3, a0, a1, a2, a3, b0, b1) \
    asm volatile("mma.sync.aligned.m16n8k16.row.col.f32.bf16.bf16.f32 " \
                 "{%0,%1,%2,%3}, {%4,%5,%6,%7}, {%8,%9}, {%0,%1,%2,%3};" \
                 : "+f"(d0), "+f"(d1), "+f"(d2), "+f"(d3) \
                 : "r"(a0), "r"(a1), "r"(a2), "r"(a3), "r"(b0), "r"(b1))
#define CP16(dst, src) \
    asm volatile("cp.async.cg.shared.global [%0], [%1], 16;" :: "r"(dst), "l"(src))
#define CP_COMMIT() asm volatile("cp.async.commit_group;")
#define CP_WAIT0()  asm volatile("cp.async.wait_group 0;" ::: "memory")

__device__ __forceinline__ void st_split_g(char* hi, char* lo, uint32_t a, float4 v) {
    __nv_bfloat16 hx = __float2bfloat16(v.x), hy = __float2bfloat16(v.y);
    __nv_bfloat16 hz = __float2bfloat16(v.z), hw = __float2bfloat16(v.w);
    __nv_bfloat16 lx = __float2bfloat16(v.x - __bfloat162float(hx));
    __nv_bfloat16 ly = __float2bfloat16(v.y - __bfloat162float(hy));
    __nv_bfloat16 lz = __float2bfloat16(v.z - __bfloat162float(hz));
    __nv_bfloat16 lw = __float2bfloat16(v.w - __bfloat162float(hw));
    uint2 h = make_uint2((uint32_t)__bfloat16_as_ushort(hx) | ((uint32_t)__bfloat16_as_ushort(hy) << 16),
                         (uint32_t)__bfloat16_as_ushort(hz) | ((uint32_t)__bfloat16_as_ushort(hw) << 16));
    uint2 l = make_uint2((uint32_t)__bfloat16_as_ushort(lx) | ((uint32_t)__bfloat16_as_ushort(ly) << 16),
                         (uint32_t)__bfloat16_as_ushort(lz) | ((uint32_t)__bfloat16_as_ushort(lw) << 16));
    *reinterpret_cast<uint2*>(hi + a) = h;
    *reinterpret_cast<uint2*>(lo + a) = l;
}

__device__ __forceinline__ constexpr int pidx(int j, int k) {
    return j * 8 - j * (j - 1) / 2 + (k - j - 1);
}

// ---------------- K0: W -> split bf16 pre-swizzled (144 CTAs) ----------------
__global__ void __launch_bounds__(256)
k0_prepW(const float* __restrict__ Wg)
{
    const int s = blockIdx.x * 256 + threadIdx.x;   // 0..36863
    const int m = s >> 12, i = s & 4095;
    const int row = i >> 5, q = i & 31;
    const float4* Wg4 = reinterpret_cast<const float4*>(Wg);
    char* hi = reinterpret_cast<char*>(Whi_g) + (size_t)m * 32768;
    char* lo = reinterpret_cast<char*>(Wlo_g) + (size_t)m * 32768;
    st_split_g(hi, lo, bswz(row, q), Wg4[(size_t)m * 4096 + i]);
}

// ---------------- K1: fully fused GEMM + phase 2 -----------------------------
__global__ void __launch_bounds__(THREADS, 1)
k1_fused(const float* __restrict__ F, float* __restrict__ out, int N)
{
    extern __shared__ char smem[];
    const uint32_t sb = smem_u32(smem);
    float* sG = reinterpret_cast<float*>(smem + SM_G);
    const float4* Fg4 = reinterpret_cast<const float4*>(F);

    const int tid  = threadIdx.x;
    const int lane = tid & 31;
    const int warp = tid >> 5;          // 0..7
    const int rg   = warp & 1;          // rows [16rg, 16rg+16)
    const int cg   = warp >> 1;         // cols [32cg, 32cg+32)
    const int n0   = blockIdx.x * NT;

    // loader geometry: 4 float4 slots per thread (slot = tid + it*256)
    int lrow[4], lq[4];
    #pragma unroll
    for (int it = 0; it < 4; ++it) {
        int s = tid + it * THREADS;
        lrow[it] = s >> 5; lq[it] = s & 31;
    }

    // prefetch raw f for m=0
    float4 fraw[4];
    #pragma unroll
    for (int it = 0; it < 4; ++it) {
        int n = n0 + lrow[it];
        fraw[it] = make_float4(0.f, 0.f, 0.f, 0.f);
        if (n < N) fraw[it] = Fg4[((size_t)n * MM + 0) * 32 + lq[it]];
    }

    float4 fsum[4];
    #pragma unroll
    for (int it = 0; it < 4; ++it) fsum[it] = make_float4(0.f, 0.f, 0.f, 0.f);

    const int a_row = 16 * rg + (lane & 15);
    const int a_ch  = lane >> 4;
    const int b_rlo = (lane & 7) + ((lane >> 4) << 3);
    const int b_ch  = (lane >> 3) & 1;

    for (int m = 0; m < MM; ++m) {
        __syncthreads();   // all LDSM of previous m done before overwriting smem

        // 1) W_m split tiles via cp.async (L2-resident)
        {
            const char* wh = reinterpret_cast<const char*>(Whi_g) + (size_t)m * 32768;
            const char* wl = reinterpret_cast<const char*>(Wlo_g) + (size_t)m * 32768;
            #pragma unroll
            for (int i = 0; i < 8; ++i) {
                uint32_t o = (uint32_t)(tid + i * 256) * 16;
                CP16(sb + SM_WHI + o, wh + o);
                CP16(sb + SM_WLO + o, wl + o);
            }
            CP_COMMIT();
        }
        // 2) convert current f, accumulate fsum, prefetch next m's raw f
        float4 fnext[4];
        #pragma unroll
        for (int it = 0; it < 4; ++it) {
            if (m + 1 < MM) {
                int n = n0 + lrow[it];
                fnext[it] = make_float4(0.f, 0.f, 0.f, 0.f);
                if (n < N) fnext[it] = Fg4[((size_t)n * MM + (m + 1)) * 32 + lq[it]];
            }
            st_split_g(smem + SM_FHI, smem + SM_FLO, bswz(lrow[it], lq[it]), fraw[it]);
            fsum[it].x += fraw[it].x; fsum[it].y += fraw[it].y;
            fsum[it].z += fraw[it].z; fsum[it].w += fraw[it].w;
        }
        CP_WAIT0();
        __syncthreads();
        #pragma unroll
        for (int it = 0; it < 4; ++it) fraw[it] = fnext[it];

        // 3) MMA: 16x32 per warp, 3 split products
        float acc[4][4];
        #pragma unroll
        for (int t = 0; t < 4; ++t)
            #pragma unroll
            for (int c = 0; c < 4; ++c) acc[t][c] = 0.f;

        #pragma unroll
        for (int kk = 0; kk < 8; ++kk) {
            uint32_t ah0, ah1, ah2, ah3, al0, al1, al2, al3;
            LDSM_X4(ah0, ah1, ah2, ah3, lmaddr(sb + SM_FHI, a_row, 2 * kk + a_ch));
            LDSM_X4(al0, al1, al2, al3, lmaddr(sb + SM_FLO, a_row, 2 * kk + a_ch));
            #pragma unroll
            for (int p = 0; p < 2; ++p) {
                const int brow = 32 * cg + 16 * p + b_rlo;
                uint32_t b0, b1, b2, b3, c0, c1, c2, c3;
                LDSM_X4(b0, b1, b2, b3, lmaddr(sb + SM_WHI, brow, 2 * kk + b_ch));
                LDSM_X4(c0, c1, c2, c3, lmaddr(sb + SM_WLO, brow, 2 * kk + b_ch));
                const int t0 = 2 * p, t1 = 2 * p + 1;
                HMMA(acc[t0][0], acc[t0][1], acc[t0][2], acc[t0][3],
                     ah0, ah1, ah2, ah3, b0, b1);
                HMMA(acc[t1][0], acc[t1][1], acc[t1][2], acc[t1][3],
                     ah0, ah1, ah2, ah3, b2, b3);
                HMMA(acc[t0][0], acc[t0][1], acc[t0][2], acc[t0][3],
                     ah0, ah1, ah2, ah3, c0, c1);
                HMMA(acc[t1][0], acc[t1][1], acc[t1][2], acc[t1][3],
                     ah0, ah1, ah2, ah3, c2, c3);
                HMMA(acc[t0][0], acc[t0][1], acc[t0][2], acc[t0][3],
                     al0, al1, al2, al3, b0, b1);
                HMMA(acc[t1][0], acc[t1][1], acc[t1][2], acc[t1][3],
                     al0, al1, al2, al3, b2, b3);
            }
        }

        // 4) relu + stash g in smem
        const int r0 = 16 * rg + (lane >> 2);
        const int cb = 32 * cg + (lane & 3) * 2;
        #pragma unroll
        for (int t = 0; t < 4; ++t) {
            const int col = cb + 8 * t;
            float2 lo = make_float2(fmaxf(acc[t][0], 0.f), fmaxf(acc[t][1], 0.f));
            float2 hi = make_float2(fmaxf(acc[t][2], 0.f), fmaxf(acc[t][3], 0.f));
            *reinterpret_cast<float2*>(sG + ((r0    ) * MM + m) * DD + col) = lo;
            *reinterpret_cast<float2*>(sG + ((r0 + 8) * MM + m) * DD + col) = hi;
        }
    }
    __syncthreads();

    // spill fsum into (dead) f region
    float4* sFs4 = reinterpret_cast<float4*>(smem + SM_FHI);
    #pragma unroll
    for (int it = 0; it < 4; ++it) sFs4[tid + it * THREADS] = fsum[it];
    __syncthreads();

    // ---------------- phase 2 (validated): edges colsum + output -------------
    const float4* sG4 = reinterpret_cast<const float4*>(sG);
    float4* out4 = reinterpret_cast<float4*>(out);

    #pragma unroll
    for (int ii = 0; ii < 4; ++ii) {
        const int i = warp * 4 + ii;
        const int n = n0 + i;

        float4 gm[MM];
        #pragma unroll
        for (int m = 0; m < MM; ++m)
            gm[m] = sG4[(i * MM + m) * 32 + lane];

        float mysA = 1.f, mysB = 1.f;
        #pragma unroll
        for (int j = 0; j < MM; ++j) {
            #pragma unroll
            for (int k = j + 1; k < MM; ++k) {
                const int p = pidx(j, k);
                float dx = gm[j].x - gm[k].x;
                float dy = gm[j].y - gm[k].y;
                float dz = gm[j].z - gm[k].z;
                float dw = gm[j].w - gm[k].w;
                float s = dx * dx;
                s = fmaf(dy, dy, s);
                s = fmaf(dz, dz, s);
                s = fmaf(dw, dw, s);
                s += __shfl_xor_sync(0xffffffffu, s, 16);
                s += __shfl_xor_sync(0xffffffffu, s, 8);
                s += __shfl_xor_sync(0xffffffffu, s, 4);
                s += __shfl_xor_sync(0xffffffffu, s, 2);
                s += __shfl_xor_sync(0xffffffffu, s, 1);
                if (p < 32) { if (lane == p)      mysA = s; }
                else        { if (lane == p - 32) mysB = s; }
            }
        }

        float xA = (mysA > 0.f) ? mysA * __frsqrt_rn(mysA) : 0.f;
        float xB = (mysB > 0.f) ? mysB * __frsqrt_rn(mysB) : 0.f;
        float eA = 1.f - __fdividef(2.f, __expf(2.f * xA) + 1.f);
        float eB = 1.f - __fdividef(2.f, __expf(2.f * xB) + 1.f);

        float cs[MM];
        #pragma unroll
        for (int k = 0; k < MM; ++k) {
            float a = 0.f;
            #pragma unroll
            for (int j = 0; j < MM; ++j) {
                if (j == k) continue;
                const int p = (j < k) ? pidx(j, k) : pidx(k, j);
                float e = (p < 32) ? __shfl_sync(0xffffffffu, eA, p)
                                   : __shfl_sync(0xffffffffu, eB, p - 32);
                a += e;
            }
            cs[k] = a;
        }

        float4 fs = sFs4[i * 32 + lane];
        float ux = 0.f, uy = 0.f, uz = 0.f, uw = 0.f;
        #pragma unroll
        for (int k = 0; k < MM; ++k) {
            ux = fmaf(cs[k], gm[k].x, ux);
            uy = fmaf(cs[k], gm[k].y, uy);
            uz = fmaf(cs[k], gm[k].z, uz);
            uw = fmaf(cs[k], gm[k].w, uw);
        }
        if (n < N) {
            float4 o;
            o.x = 0.5f * (fs.x + ux);
            o.y = 0.5f * (fs.y + uy);
            o.z = 0.5f * (fs.z + uz);
            o.w = 0.5f * (fs.w + uw);
            out4[(size_t)n * 32 + lane] = o;
        }
    }
}

// ----------------------------------------------------------------------------
extern "C" void kernel_launch(void* const* d_in, const int* in_sizes, int n_in,
                              void* d_out, int out_size) {
    const float* F = (const float*)d_in[0];   // [N,9,128] fp32
    const float* W = (const float*)d_in[1];   // [9,128,128] fp32
    float* out = (float*)d_out;               // [N,128] fp32
    const int N = in_sizes[0] / (MM * DD);

    cudaFuncSetAttribute(k1_fused, cudaFuncAttributeMaxDynamicSharedMemorySize, SMEM_BYTES);

    k0_prepW<<<144, 256>>>(W);
    const int grid = (N + NT - 1) / NT;
    k1_fused<<<grid, THREADS, SMEM_BYTES>>>(F, out, N);
}

// round 8
// speedup vs baseline: 1.1294x; 1.1294x over previous
#include <cuda_runtime.h>
#include <cuda_bf16.h>
#include <cstdint>

#define MM 9
#define DD 128
#define NMAX 8192

// ---------------- global scratch (static, no dynamic alloc) ----------------
static __device__ __align__(128) __nv_bfloat16 Whi_g[MM * 128 * 128];
static __device__ __align__(128) __nv_bfloat16 Wlo_g[MM * 128 * 128];
static __device__ __align__(128) float g_g[NMAX * MM * DD];

// ---------------- helpers ---------------------------------------------------
__device__ __forceinline__ uint32_t bswz(int row, int q) {
    int c = q >> 1;
    int cs = (c & 8) | ((c & 7) ^ (row & 7));
    return (uint32_t)(row * 256 + cs * 16 + (q & 1) * 8);
}
__device__ __forceinline__ uint32_t lmaddr(uint32_t base, int row, int chunk) {
    int cs = (chunk & 8) | ((chunk & 7) ^ (row & 7));
    return base + (uint32_t)(row * 256 + cs * 16);
}
__device__ __forceinline__ uint32_t smem_u32(const void* p) {
    uint32_t a;
    asm("{ .reg .u64 t; cvta.to.shared.u64 t, %1; cvt.u32.u64 %0, t; }" : "=r"(a) : "l"(p));
    return a;
}
#define LDSM_X4(r0, r1, r2, r3, a) \
    asm volatile("ldmatrix.sync.aligned.m8n8.x4.shared.b16 {%0,%1,%2,%3}, [%4];" \
                 : "=r"(r0), "=r"(r1), "=r"(r2), "=r"(r3) : "r"(a))
#define HMMA(d0, d1, d2, d3, a0, a1, a2, a3, b0, b1) \
    asm volatile("mma.sync.aligned.m16n8k16.row.col.f32.bf16.bf16.f32 " \
                 "{%0,%1,%2,%3}, {%4,%5,%6,%7}, {%8,%9}, {%0,%1,%2,%3};" \
                 : "+f"(d0), "+f"(d1), "+f"(d2), "+f"(d3) \
                 : "r"(a0), "r"(a1), "r"(a2), "r"(a3), "r"(b0), "r"(b1))
#define CP16(dst, src) \
    asm volatile("cp.async.cg.shared.global [%0], [%1], 16;" :: "r"(dst), "l"(src))
#define CP_COMMIT() asm volatile("cp.async.commit_group;")
#define CP_WAIT0()  asm volatile("cp.async.wait_group 0;" ::: "memory")

__device__ __forceinline__ void st_split_g(char* hi, char* lo, uint32_t a, float4 v) {
    __nv_bfloat16 hx = __float2bfloat16(v.x), hy = __float2bfloat16(v.y);
    __nv_bfloat16 hz = __float2bfloat16(v.z), hw = __float2bfloat16(v.w);
    __nv_bfloat16 lx = __float2bfloat16(v.x - __bfloat162float(hx));
    __nv_bfloat16 ly = __float2bfloat16(v.y - __bfloat162float(hy));
    __nv_bfloat16 lz = __float2bfloat16(v.z - __bfloat162float(hz));
    __nv_bfloat16 lw = __float2bfloat16(v.w - __bfloat162float(hw));
    uint2 h = make_uint2((uint32_t)__bfloat16_as_ushort(hx) | ((uint32_t)__bfloat16_as_ushort(hy) << 16),
                         (uint32_t)__bfloat16_as_ushort(hz) | ((uint32_t)__bfloat16_as_ushort(hw) << 16));
    uint2 l = make_uint2((uint32_t)__bfloat16_as_ushort(lx) | ((uint32_t)__bfloat16_as_ushort(ly) << 16),
                         (uint32_t)__bfloat16_as_ushort(lz) | ((uint32_t)__bfloat16_as_ushort(lw) << 16));
    *reinterpret_cast<uint2*>(hi + a) = h;
    *reinterpret_cast<uint2*>(lo + a) = l;
}

__device__ __forceinline__ constexpr int pidx(int j, int k) {
    return j * 8 - j * (j - 1) / 2 + (k - j - 1);
}

// ---------------- K0: W -> split bf16 pre-swizzled (144 CTAs) ----------------
__global__ void __launch_bounds__(256)
k0_prepW(const float* __restrict__ Wg)
{
    const int s = blockIdx.x * 256 + threadIdx.x;   // 0..36863 == 9*4096
    const int m = s >> 12, i = s & 4095;
    const int row = i >> 5, q = i & 31;
    const float4* Wg4 = reinterpret_cast<const float4*>(Wg);
    char* hi = reinterpret_cast<char*>(Whi_g) + (size_t)m * 32768;
    char* lo = reinterpret_cast<char*>(Wlo_g) + (size_t)m * 32768;
    st_split_g(hi, lo, bswz(row, q), Wg4[(size_t)m * 4096 + i]);
}

// ---------------- K1: persistent-W split-bf16 HMMA ---------------------------
// grid (32, 9), 256 thr; smem: fhi 16K | flo 16K | Whi 32K | Wlo 32K = 96K
#define SM_FHI 0
#define SM_FLO 16384
#define SM_WHI 32768
#define SM_WLO 65536
#define K1_SMEM 98304
#define NTILE_STRIDE 32

__global__ void __launch_bounds__(256, 2)
k1_gemm(const float* __restrict__ F, int N)
{
    extern __shared__ char smem[];
    const uint32_t sb = smem_u32(smem);
    const int tid  = threadIdx.x;
    const int lane = tid & 31;
    const int warp = tid >> 5;          // 0..7
    const int rg   = warp & 3;          // rows [16rg, 16rg+16)
    const int cg   = warp >> 2;         // cols [64cg, 64cg+64)
    const int m    = blockIdx.y;
    const int ntiles = (N + 63) / 64;
    const float4* Fg4 = reinterpret_cast<const float4*>(F);

    // W_m split tiles, loaded ONCE per CTA
    {
        const char* wh = reinterpret_cast<const char*>(Whi_g) + (size_t)m * 32768;
        const char* wl = reinterpret_cast<const char*>(Wlo_g) + (size_t)m * 32768;
        #pragma unroll
        for (int i = 0; i < 8; ++i) {
            uint32_t o = (uint32_t)(tid + i * 256) * 16;
            CP16(sb + SM_WHI + o, wh + o);
            CP16(sb + SM_WLO + o, wl + o);
        }
        CP_COMMIT();
    }

    // loader geometry: 8 float4 slots per thread
    int lrow[8], lq[8];
    #pragma unroll
    for (int it = 0; it < 8; ++it) {
        int s = tid + it * 256;          // 0..2047
        lrow[it] = s >> 5; lq[it] = s & 31;
    }

    const int a_row = 16 * rg + (lane & 15);
    const int a_ch  = lane >> 4;
    const int b_rlo = (lane & 7) + ((lane >> 4) << 3);
    const int b_ch  = (lane >> 3) & 1;

    // prefetch f for first tile
    float4 fraw[8];
    {
        const int n0 = blockIdx.x * 64;
        #pragma unroll
        for (int it = 0; it < 8; ++it) {
            int n = n0 + lrow[it];
            fraw[it] = make_float4(0.f, 0.f, 0.f, 0.f);
            if (n < N) fraw[it] = Fg4[((size_t)n * MM + m) * 32 + lq[it]];
        }
    }
    CP_WAIT0();
    __syncthreads();           // W resident

    for (int t = blockIdx.x; t < ntiles; t += NTILE_STRIDE) {
        const int n0 = t * 64;

        // convert current f tile into split smem
        #pragma unroll
        for (int it = 0; it < 8; ++it)
            st_split_g(smem + SM_FHI, smem + SM_FLO, bswz(lrow[it], lq[it]), fraw[it]);
        __syncthreads();

        // prefetch next tile's raw f (overlaps the MMA chain below)
        const int tn = t + NTILE_STRIDE;
        if (tn < ntiles) {
            const int nn0 = tn * 64;
            #pragma unroll
            for (int it = 0; it < 8; ++it) {
                int n = nn0 + lrow[it];
                fraw[it] = make_float4(0.f, 0.f, 0.f, 0.f);
                if (n < N) fraw[it] = Fg4[((size_t)n * MM + m) * 32 + lq[it]];
            }
        }

        float acc[8][4];
        #pragma unroll
        for (int q = 0; q < 8; ++q)
            #pragma unroll
            for (int c = 0; c < 4; ++c) acc[q][c] = 0.f;

        #pragma unroll
        for (int kk = 0; kk < 8; ++kk) {
            uint32_t ah0, ah1, ah2, ah3, al0, al1, al2, al3;
            LDSM_X4(ah0, ah1, ah2, ah3, lmaddr(sb + SM_FHI, a_row, 2 * kk + a_ch));
            LDSM_X4(al0, al1, al2, al3, lmaddr(sb + SM_FLO, a_row, 2 * kk + a_ch));
            #pragma unroll
            for (int p = 0; p < 4; ++p) {
                const int brow = 64 * cg + 16 * p + b_rlo;
                uint32_t b0, b1, b2, b3, c0, c1, c2, c3;
                LDSM_X4(b0, b1, b2, b3, lmaddr(sb + SM_WHI, brow, 2 * kk + b_ch));
                LDSM_X4(c0, c1, c2, c3, lmaddr(sb + SM_WLO, brow, 2 * kk + b_ch));
                const int t0 = 2 * p, t1 = 2 * p + 1;
                HMMA(acc[t0][0], acc[t0][1], acc[t0][2], acc[t0][3],
                     ah0, ah1, ah2, ah3, b0, b1);
                HMMA(acc[t1][0], acc[t1][1], acc[t1][2], acc[t1][3],
                     ah0, ah1, ah2, ah3, b2, b3);
                HMMA(acc[t0][0], acc[t0][1], acc[t0][2], acc[t0][3],
                     ah0, ah1, ah2, ah3, c0, c1);
                HMMA(acc[t1][0], acc[t1][1], acc[t1][2], acc[t1][3],
                     ah0, ah1, ah2, ah3, c2, c3);
                HMMA(acc[t0][0], acc[t0][1], acc[t0][2], acc[t0][3],
                     al0, al1, al2, al3, b0, b1);
                HMMA(acc[t1][0], acc[t1][1], acc[t1][2], acc[t1][3],
                     al0, al1, al2, al3, b2, b3);
            }
        }

        // relu + store g[n][m][col]
        const int r0 = n0 + 16 * rg + (lane >> 2);
        const int cb = 64 * cg + (lane & 3) * 2;
        #pragma unroll
        for (int q = 0; q < 8; ++q) {
            const int col = cb + 8 * q;
            if (r0 < N) {
                float2 v = make_float2(fmaxf(acc[q][0], 0.f), fmaxf(acc[q][1], 0.f));
                *reinterpret_cast<float2*>(g_g + ((size_t)r0 * MM + m) * DD + col) = v;
            }
            if (r0 + 8 < N) {
                float2 v = make_float2(fmaxf(acc[q][2], 0.f), fmaxf(acc[q][3], 0.f));
                *reinterpret_cast<float2*>(g_g + ((size_t)(r0 + 8) * MM + m) * DD + col) = v;
            }
        }
        __syncthreads();   // f smem consumed; safe to overwrite next iteration
    }
}

// ---------------- K2: edges column-sum + fsum + output -----------------------
__global__ void __launch_bounds__(256)
k2_phase2(const float* __restrict__ F, float* __restrict__ out, int N)
{
    const int lane = threadIdx.x & 31;
    const int warp = threadIdx.x >> 5;
    const int n0   = blockIdx.x * 16;
    const float4* g4  = reinterpret_cast<const float4*>(g_g);
    const float4* Fg4 = reinterpret_cast<const float4*>(F);
    float4* out4 = reinterpret_cast<float4*>(out);

    #pragma unroll
    for (int ii = 0; ii < 2; ++ii) {
        const int n = n0 + warp * 2 + ii;
        if (n >= N) continue;

        float4 gm[MM];
        #pragma unroll
        for (int m = 0; m < MM; ++m)
            gm[m] = g4[((size_t)n * MM + m) * 32 + lane];

        // fsum over m (exact fp32)
        float4 fs = Fg4[((size_t)n * MM) * 32 + lane];
        #pragma unroll
        for (int m = 1; m < MM; ++m) {
            float4 v = Fg4[((size_t)n * MM + m) * 32 + lane];
            fs.x += v.x; fs.y += v.y; fs.z += v.z; fs.w += v.w;
        }

        float mysA = 1.f, mysB = 1.f;
        #pragma unroll
        for (int j = 0; j < MM; ++j) {
            #pragma unroll
            for (int k = j + 1; k < MM; ++k) {
                const int p = pidx(j, k);
                float dx = gm[j].x - gm[k].x;
                float dy = gm[j].y - gm[k].y;
                float dz = gm[j].z - gm[k].z;
                float dw = gm[j].w - gm[k].w;
                float s = dx * dx;
                s = fmaf(dy, dy, s);
                s = fmaf(dz, dz, s);
                s = fmaf(dw, dw, s);
                s += __shfl_xor_sync(0xffffffffu, s, 16);
                s += __shfl_xor_sync(0xffffffffu, s, 8);
                s += __shfl_xor_sync(0xffffffffu, s, 4);
                s += __shfl_xor_sync(0xffffffffu, s, 2);
                s += __shfl_xor_sync(0xffffffffu, s, 1);
                if (p < 32) { if (lane == p)      mysA = s; }
                else        { if (lane == p - 32) mysB = s; }
            }
        }

        float xA = (mysA > 0.f) ? mysA * __frsqrt_rn(mysA) : 0.f;
        float xB = (mysB > 0.f) ? mysB * __frsqrt_rn(mysB) : 0.f;
        float eA = 1.f - __fdividef(2.f, __expf(2.f * xA) + 1.f);
        float eB = 1.f - __fdividef(2.f, __expf(2.f * xB) + 1.f);

        float cs[MM];
        #pragma unroll
        for (int k = 0; k < MM; ++k) {
            float a = 0.f;
            #pragma unroll
            for (int j = 0; j < MM; ++j) {
                if (j == k) continue;
                const int p = (j < k) ? pidx(j, k) : pidx(k, j);
                float e = (p < 32) ? __shfl_sync(0xffffffffu, eA, p)
                                   : __shfl_sync(0xffffffffu, eB, p - 32);
                a += e;
            }
            cs[k] = a;
        }

        float ux = 0.f, uy = 0.f, uz = 0.f, uw = 0.f;
        #pragma unroll
        for (int k = 0; k < MM; ++k) {
            ux = fmaf(cs[k], gm[k].x, ux);
            uy = fmaf(cs[k], gm[k].y, uy);
            uz = fmaf(cs[k], gm[k].z, uz);
            uw = fmaf(cs[k], gm[k].w, uw);
        }
        float4 o;
        o.x = 0.5f * (fs.x + ux);
        o.y = 0.5f * (fs.y + uy);
        o.z = 0.5f * (fs.z + uz);
        o.w = 0.5f * (fs.w + uw);
        out4[(size_t)n * 32 + lane] = o;
    }
}

// ----------------------------------------------------------------------------
extern "C" void kernel_launch(void* const* d_in, const int* in_sizes, int n_in,
                              void* d_out, int out_size) {
    const float* F = (const float*)d_in[0];   // [N,9,128] fp32
    const float* W = (const float*)d_in[1];   // [9,128,128] fp32
    float* out = (float*)d_out;               // [N,128] fp32
    const int N = in_sizes[0] / (MM * DD);

    cudaFuncSetAttribute(k1_gemm, cudaFuncAttributeMaxDynamicSharedMemorySize, K1_SMEM);

    k0_prepW<<<144, 256>>>(W);
    dim3 g1(NTILE_STRIDE, MM);
    k1_gemm<<<g1, 256, K1_SMEM>>>(F, N);
    k2_phase2<<<(N + 15) / 16, 256>>>(F, out, N);
}